// round 16
// baseline (speedup 1.0000x reference)
#include <cuda_runtime.h>
#include <math.h>

#define IMG_H 200
#define IMG_W 200
#define IMG_C 256
#define PIX_BYTES (IMG_C * 4)   // 1024 bytes per pixel

// Champion (R7/R12) memory structure with warp-autonomous geometry:
// lane l computes geometry for the warp's l-th cell (all lanes in parallel,
// once per warp), broadcast per cell via __shfl_sync. No smem, no
// __syncthreads -> warps begin streaming loads immediately.
__global__ __launch_bounds__(256, 5) void roipool_kernel(
        const float* __restrict__ img,
        const float* __restrict__ rois,
        float* __restrict__ out,
        int ps) {
    const int r    = blockIdx.x;
    const int warp = threadIdx.x >> 5;
    const int lane = threadIdx.x & 31;
    const int pp   = ps * ps;

    const float4 rv = reinterpret_cast<const float4*>(rois)[r];
    const int x = (int)rv.x;
    const int y = (int)rv.y;
    const int w = (int)rv.z;
    const int h = (int)rv.w;

    // ---- per-lane geometry: cell = warp + lane*8 ----
    unsigned m00 = 0, m01 = 0, m10 = 0, m11 = 0;
    float mwx = 0.0f, mwy = 0.0f;
    {
        const int myc = warp + (lane << 3);
        if (myc < pp) {
            const int py = myc / ps;
            const int px = myc - py * ps;

            const float sy = (float)h / (float)ps;
            const float sx = (float)w / (float)ps;
            const float src_y = (float)py * sy;
            const float src_x = (float)px * sx;
            const int y0 = (int)floorf(src_y);
            const int x0 = (int)floorf(src_x);

            const int gy0 = min(max(y + min(max(y0,     0), h - 1), 0), IMG_H - 1);
            const int gy1 = min(max(y + min(max(y0 + 1, 0), h - 1), 0), IMG_H - 1);
            const int gx0 = min(max(x + min(max(x0,     0), w - 1), 0), IMG_W - 1);
            const int gx1 = min(max(x + min(max(x0 + 1, 0), w - 1), 0), IMG_W - 1);

            m00 = (unsigned)(gy0 * IMG_W + gx0) * PIX_BYTES;
            m01 = (unsigned)(gy0 * IMG_W + gx1) * PIX_BYTES;
            m10 = (unsigned)(gy1 * IMG_W + gx0) * PIX_BYTES;
            m11 = (unsigned)(gy1 * IMG_W + gx1) * PIX_BYTES;
            mwx = src_x - (float)x0;
            mwy = src_y - (float)y0;
        }
    }

    const int ncell = (pp - warp + 7) >> 3;   // cells for this warp (uniform in warp)

    const unsigned ca = (unsigned)lane * 16u;   // channel-half A byte offset
    const unsigned cb = ca + 512u;              // channel-half B
    const char* __restrict__ ib = reinterpret_cast<const char*>(img);
    char* __restrict__ ob = reinterpret_cast<char*>(out)
                          + (unsigned)r * (unsigned)pp * PIX_BYTES;

#define LD4(off) (*reinterpret_cast<const float4*>(ib + (off)))

    for (int j = 0; j < ncell; j++) {
        const unsigned o00 = __shfl_sync(0xFFFFFFFFu, m00, j);
        const unsigned o01 = __shfl_sync(0xFFFFFFFFu, m01, j);
        const unsigned o10 = __shfl_sync(0xFFFFFFFFu, m10, j);
        const unsigned o11 = __shfl_sync(0xFFFFFFFFu, m11, j);
        const float    wx  = __shfl_sync(0xFFFFFFFFu, mwx, j);
        const float    wy  = __shfl_sync(0xFFFFFFFFu, mwy, j);

        const int cell = warp + (j << 3);
        char* oc = ob + (unsigned)cell * PIX_BYTES;
        float4* __restrict__ oa  = reinterpret_cast<float4*>(oc + ca);
        float4* __restrict__ obp = reinterpret_cast<float4*>(oc + cb);

        const bool zx = (wx == 0.0f);
        const bool zy = (wy == 0.0f);

        if (zx && zy) {
            *oa  = LD4(o00 + ca);
            *obp = LD4(o00 + cb);
        } else if (zx) {
            const float4 a00 = LD4(o00 + ca);
            const float4 a10 = LD4(o10 + ca);
            const float4 b00 = LD4(o00 + cb);
            const float4 b10 = LD4(o10 + cb);
            const float omwy = 1.0f - wy;
            float4 ra, rb;
            ra.x = a00.x * omwy + a10.x * wy;
            ra.y = a00.y * omwy + a10.y * wy;
            ra.z = a00.z * omwy + a10.z * wy;
            ra.w = a00.w * omwy + a10.w * wy;
            rb.x = b00.x * omwy + b10.x * wy;
            rb.y = b00.y * omwy + b10.y * wy;
            rb.z = b00.z * omwy + b10.z * wy;
            rb.w = b00.w * omwy + b10.w * wy;
            *oa = ra; *obp = rb;
        } else if (zy) {
            const float4 a00 = LD4(o00 + ca);
            const float4 a01 = LD4(o01 + ca);
            const float4 b00 = LD4(o00 + cb);
            const float4 b01 = LD4(o01 + cb);
            const float omwx = 1.0f - wx;
            float4 ra, rb;
            ra.x = a00.x * omwx + a01.x * wx;
            ra.y = a00.y * omwx + a01.y * wx;
            ra.z = a00.z * omwx + a01.z * wx;
            ra.w = a00.w * omwx + a01.w * wx;
            rb.x = b00.x * omwx + b01.x * wx;
            rb.y = b00.y * omwx + b01.y * wx;
            rb.z = b00.z * omwx + b01.z * wx;
            rb.w = b00.w * omwx + b01.w * wx;
            *oa = ra; *obp = rb;
        } else {
            const float4 a00 = LD4(o00 + ca);
            const float4 a01 = LD4(o01 + ca);
            const float4 a10 = LD4(o10 + ca);
            const float4 a11 = LD4(o11 + ca);
            const float4 b00 = LD4(o00 + cb);
            const float4 b01 = LD4(o01 + cb);
            const float4 b10 = LD4(o10 + cb);
            const float4 b11 = LD4(o11 + cb);

            const float omwx = 1.0f - wx;
            const float omwy = 1.0f - wy;
            float4 ra, rb;
            {
                float t, b;
                t = a00.x * omwx + a01.x * wx; b = a10.x * omwx + a11.x * wx; ra.x = t * omwy + b * wy;
                t = a00.y * omwx + a01.y * wx; b = a10.y * omwx + a11.y * wx; ra.y = t * omwy + b * wy;
                t = a00.z * omwx + a01.z * wx; b = a10.z * omwx + a11.z * wx; ra.z = t * omwy + b * wy;
                t = a00.w * omwx + a01.w * wx; b = a10.w * omwx + a11.w * wx; ra.w = t * omwy + b * wy;

                t = b00.x * omwx + b01.x * wx; b = b10.x * omwx + b11.x * wx; rb.x = t * omwy + b * wy;
                t = b00.y * omwx + b01.y * wx; b = b10.y * omwx + b11.y * wx; rb.y = t * omwy + b * wy;
                t = b00.z * omwx + b01.z * wx; b = b10.z * omwx + b11.z * wx; rb.z = t * omwy + b * wy;
                t = b00.w * omwx + b01.w * wx; b = b10.w * omwx + b11.w * wx; rb.w = t * omwy + b * wy;
            }
            *oa = ra; *obp = rb;
        }
    }
#undef LD4
}

extern "C" void kernel_launch(void* const* d_in, const int* in_sizes, int n_in,
                              void* d_out, int out_size) {
    const float* img  = (const float*)d_in[0];
    const float* rois = (const float*)d_in[1];
    float* out = (float*)d_out;

    const int n_rois = in_sizes[1] / 4;
    const int pp = out_size / (n_rois * IMG_C);
    int ps = (int)(sqrtf((float)pp) + 0.5f);
    if (ps < 1) ps = 1;
    if (ps > 16) ps = 16;   // 32 lanes cover up to 8 cells/warp for ps<=16

    roipool_kernel<<<n_rois, 256>>>(img, rois, out, ps);
}

// round 17
// speedup vs baseline: 1.1152x; 1.1152x over previous
#include <cuda_runtime.h>
#include <math.h>

#define IMG_H 200
#define IMG_W 200
#define IMG_C 256
#define PIX_BYTES (IMG_C * 4)   // 1024 bytes per pixel
#define MAX_PP 64               // supports ps up to 8

struct CellGeom {
    unsigned o00, o01, o10, o11;  // BYTE offsets of the 4 corner pixels
    float wx, wy;
};

// R7 champion, templated on PS: compile-time divisions (mul-shift) and an
// analyzable trip count so ptxas can software-pipeline across unrolled
// iterations (#pragma unroll 2 -> two cells' load batches interleaved).
template <int PS>
__global__ __launch_bounds__(256, 4) void roipool_kernel(
        const float* __restrict__ img,
        const float* __restrict__ rois,
        float* __restrict__ out,
        int ps_rt) {
    __shared__ CellGeom geom[MAX_PP];

    const int psv = (PS > 0) ? PS : ps_rt;
    const int pp  = psv * psv;

    const int r    = blockIdx.x;
    const int warp = threadIdx.x >> 5;
    const int lane = threadIdx.x & 31;

    const float4 rv = reinterpret_cast<const float4*>(rois)[r];
    const int x = (int)rv.x;
    const int y = (int)rv.y;
    const int w = (int)rv.z;
    const int h = (int)rv.w;

    if (threadIdx.x < pp) {
        const int cell = threadIdx.x;
        const int py = cell / psv;            // mul-shift when PS>0
        const int px = cell - py * psv;

        const float sy = (float)h / (float)psv;
        const float sx = (float)w / (float)psv;
        const float src_y = (float)py * sy;
        const float src_x = (float)px * sx;
        const int y0 = (int)floorf(src_y);
        const int x0 = (int)floorf(src_x);

        const int gy0 = min(max(y + min(max(y0,     0), h - 1), 0), IMG_H - 1);
        const int gy1 = min(max(y + min(max(y0 + 1, 0), h - 1), 0), IMG_H - 1);
        const int gx0 = min(max(x + min(max(x0,     0), w - 1), 0), IMG_W - 1);
        const int gx1 = min(max(x + min(max(x0 + 1, 0), w - 1), 0), IMG_W - 1);

        CellGeom g;
        g.o00 = (unsigned)(gy0 * IMG_W + gx0) * PIX_BYTES;
        g.o01 = (unsigned)(gy0 * IMG_W + gx1) * PIX_BYTES;
        g.o10 = (unsigned)(gy1 * IMG_W + gx0) * PIX_BYTES;
        g.o11 = (unsigned)(gy1 * IMG_W + gx1) * PIX_BYTES;
        g.wx  = src_x - (float)x0;
        g.wy  = src_y - (float)y0;
        geom[cell] = g;
    }
    __syncthreads();

    const char* __restrict__ ib = reinterpret_cast<const char*>(img);
    char* __restrict__ ob = reinterpret_cast<char*>(out)
                          + (unsigned)r * (unsigned)pp * PIX_BYTES;

    const unsigned ca = (unsigned)lane * 16u;   // channel-half A byte offset
    const unsigned cb = ca + 512u;              // channel-half B

#define LD4(off) (*reinterpret_cast<const float4*>(ib + (off)))

#pragma unroll 2
    for (int cell = warp; cell < pp; cell += 8) {
        const CellGeom g = geom[cell];          // broadcast LDS
        char* oc = ob + (unsigned)cell * PIX_BYTES;
        float4* __restrict__ oa  = reinterpret_cast<float4*>(oc + ca);
        float4* __restrict__ obp = reinterpret_cast<float4*>(oc + cb);

        const float wx = g.wx, wy = g.wy;
        const bool zx = (wx == 0.0f);
        const bool zy = (wy == 0.0f);

        if (zx && zy) {
            *oa  = LD4(g.o00 + ca);
            *obp = LD4(g.o00 + cb);
        } else if (zx) {
            const float4 a00 = LD4(g.o00 + ca);
            const float4 a10 = LD4(g.o10 + ca);
            const float4 b00 = LD4(g.o00 + cb);
            const float4 b10 = LD4(g.o10 + cb);
            const float omwy = 1.0f - wy;
            float4 ra, rb;
            ra.x = a00.x * omwy + a10.x * wy;
            ra.y = a00.y * omwy + a10.y * wy;
            ra.z = a00.z * omwy + a10.z * wy;
            ra.w = a00.w * omwy + a10.w * wy;
            rb.x = b00.x * omwy + b10.x * wy;
            rb.y = b00.y * omwy + b10.y * wy;
            rb.z = b00.z * omwy + b10.z * wy;
            rb.w = b00.w * omwy + b10.w * wy;
            *oa = ra; *obp = rb;
        } else if (zy) {
            const float4 a00 = LD4(g.o00 + ca);
            const float4 a01 = LD4(g.o01 + ca);
            const float4 b00 = LD4(g.o00 + cb);
            const float4 b01 = LD4(g.o01 + cb);
            const float omwx = 1.0f - wx;
            float4 ra, rb;
            ra.x = a00.x * omwx + a01.x * wx;
            ra.y = a00.y * omwx + a01.y * wx;
            ra.z = a00.z * omwx + a01.z * wx;
            ra.w = a00.w * omwx + a01.w * wx;
            rb.x = b00.x * omwx + b01.x * wx;
            rb.y = b00.y * omwx + b01.y * wx;
            rb.z = b00.z * omwx + b01.z * wx;
            rb.w = b00.w * omwx + b01.w * wx;
            *oa = ra; *obp = rb;
        } else {
            const float4 a00 = LD4(g.o00 + ca);
            const float4 a01 = LD4(g.o01 + ca);
            const float4 a10 = LD4(g.o10 + ca);
            const float4 a11 = LD4(g.o11 + ca);
            const float4 b00 = LD4(g.o00 + cb);
            const float4 b01 = LD4(g.o01 + cb);
            const float4 b10 = LD4(g.o10 + cb);
            const float4 b11 = LD4(g.o11 + cb);

            const float omwx = 1.0f - wx;
            const float omwy = 1.0f - wy;
            float4 ra, rb;
            {
                float t, b;
                t = a00.x * omwx + a01.x * wx; b = a10.x * omwx + a11.x * wx; ra.x = t * omwy + b * wy;
                t = a00.y * omwx + a01.y * wx; b = a10.y * omwx + a11.y * wx; ra.y = t * omwy + b * wy;
                t = a00.z * omwx + a01.z * wx; b = a10.z * omwx + a11.z * wx; ra.z = t * omwy + b * wy;
                t = a00.w * omwx + a01.w * wx; b = a10.w * omwx + a11.w * wx; ra.w = t * omwy + b * wy;

                t = b00.x * omwx + b01.x * wx; b = b10.x * omwx + b11.x * wx; rb.x = t * omwy + b * wy;
                t = b00.y * omwx + b01.y * wx; b = b10.y * omwx + b11.y * wx; rb.y = t * omwy + b * wy;
                t = b00.z * omwx + b01.z * wx; b = b10.z * omwx + b11.z * wx; rb.z = t * omwy + b * wy;
                t = b00.w * omwx + b01.w * wx; b = b10.w * omwx + b11.w * wx; rb.w = t * omwy + b * wy;
            }
            *oa = ra; *obp = rb;
        }
    }
#undef LD4
}

extern "C" void kernel_launch(void* const* d_in, const int* in_sizes, int n_in,
                              void* d_out, int out_size) {
    const float* img  = (const float*)d_in[0];
    const float* rois = (const float*)d_in[1];
    float* out = (float*)d_out;

    const int n_rois = in_sizes[1] / 4;
    const int pp = out_size / (n_rois * IMG_C);
    int ps = (int)(sqrtf((float)pp) + 0.5f);
    if (ps < 1) ps = 1;
    if (ps * ps > MAX_PP) ps = 8;

    if (ps == 7) {
        roipool_kernel<7><<<n_rois, 256>>>(img, rois, out, 7);
    } else {
        roipool_kernel<0><<<n_rois, 256>>>(img, rois, out, ps);
    }
}